// round 11
// baseline (speedup 1.0000x reference)
#include <cuda_runtime.h>
#include <cuda_bf16.h>
#include <cstdint>

#define BB 2
#define NQ 256
#define ED 512
#define HH 150
#define HP 152

#define P1 272            // A1/B1 pitch (bytes)
#define PH 304            // HtA/HtB/W2s pitch (bytes)
#define PG 272            // g bf16 staging pitch (bytes)

// ---------------- device scratch ----------------
__device__ __nv_bfloat16 d_w1ctb[HP*ED];      // W1c^T bf16 [h][e]
__device__ __nv_bfloat16 d_w2t[HP*HP];        // W2^T bf16 [o][k]
__device__ float         d_hip[2*BB*NQ*HP];   // hi+b1 partials
__device__ float         d_hjp[2*BB*NQ*HP];   // hj partials

// ---------------- smem layout (bytes) ----------------
#define SM_HIS  0                       // 9728
#define SM_HJS  9728                    // 9728
#define SM_B2S  19456                   // 608
#define SM_W3S  20064                   // 608
#define SM_MIS  20672                   // 64
#define SM_MJS  20736                   // 64
#define SM_SRED 20800                   // 2048
#define SM_U    22848
// stage-1 union
#define OFF_A10 0                       // 69632
#define OFF_A11 69632                   // 69632 -> 139264
#define OFF_B1  139264                  // 41344 -> 180608
#define OFF_G0  180608                  // 8704
#define OFF_G1  189312                  // 8704 -> 198016
// stage-2 union (aliases)
#define OFF_W2  0                       // 46208 (inside dead A10)
#define OFF_HA  46208                   // 77824 -> 124032
#define OFF_HB  124032                  // 77824 -> 201856
#define SMEM_BYTES (SM_U + 201856)      // 224704

__device__ __forceinline__ uint32_t smem_u32(const void* p) {
    uint32_t a;
    asm("{ .reg .u64 t; cvta.to.shared.u64 t, %1; cvt.u32.u64 %0, t; }" : "=r"(a) : "l"(p));
    return a;
}
__device__ __forceinline__ void ldsm_x4(uint32_t& r0, uint32_t& r1, uint32_t& r2, uint32_t& r3,
                                        uint32_t addr) {
    asm volatile("ldmatrix.sync.aligned.m8n8.x4.shared.b16 {%0,%1,%2,%3}, [%4];"
                 : "=r"(r0), "=r"(r1), "=r"(r2), "=r"(r3) : "r"(addr));
}
__device__ __forceinline__ void ldsm_x2(uint32_t& r0, uint32_t& r1, uint32_t addr) {
    asm volatile("ldmatrix.sync.aligned.m8n8.x2.shared.b16 {%0,%1}, [%2];"
                 : "=r"(r0), "=r"(r1) : "r"(addr));
}
__device__ __forceinline__ void ldsm_x1(uint32_t& r0, uint32_t addr) {
    asm volatile("ldmatrix.sync.aligned.m8n8.x1.shared.b16 {%0}, [%1];"
                 : "=r"(r0) : "r"(addr));
}
__device__ __forceinline__ void mma16816(float* d, uint32_t a0, uint32_t a1, uint32_t a2,
                                         uint32_t a3, uint32_t b0, uint32_t b1) {
    asm volatile("mma.sync.aligned.m16n8k16.row.col.f32.bf16.bf16.f32 "
                 "{%0,%1,%2,%3}, {%4,%5,%6,%7}, {%8,%9}, {%0,%1,%2,%3};"
                 : "+f"(d[0]), "+f"(d[1]), "+f"(d[2]), "+f"(d[3])
                 : "r"(a0), "r"(a1), "r"(a2), "r"(a3), "r"(b0), "r"(b1));
}
__device__ __forceinline__ void mma16808(float* d, uint32_t a0, uint32_t a1, uint32_t b0) {
    asm volatile("mma.sync.aligned.m16n8k8.row.col.f32.bf16.bf16.f32 "
                 "{%0,%1,%2,%3}, {%4,%5}, {%6}, {%0,%1,%2,%3};"
                 : "+f"(d[0]), "+f"(d[1]), "+f"(d[2]), "+f"(d[3])
                 : "r"(a0), "r"(a1), "r"(b0));
}
__device__ __forceinline__ uint32_t mulbf2(uint32_t a, uint32_t b) {
    uint32_t r;
    asm("mul.bf16x2 %0, %1, %2;" : "=r"(r) : "r"(a), "r"(b));
    return r;
}
__device__ __forceinline__ float2 bf2_to_f2(uint32_t u) {
    __nv_bfloat162 h = *(__nv_bfloat162*)&u;
    return __bfloat1622float2(h);
}
__device__ __forceinline__ uint32_t pack_bf2(float x, float y) {
    __nv_bfloat162 p = __floats2bfloat162_rn(x, y);
    return *(uint32_t*)&p;
}

// ---------------- prekernels ----------------
__global__ void prep_w1ct(const float* __restrict__ W1) {
    __shared__ float tile[32][33];
    int e0 = blockIdx.x * 32, h0 = blockIdx.y * 32;
    int tx = threadIdx.x, ty = threadIdx.y;
    int h = h0 + tx, e = e0 + ty;
    tile[ty][tx] = (h < HH) ? W1[(size_t)(2*ED + e)*HH + h] : 0.f;
    __syncthreads();
    int ho = h0 + ty, eo = e0 + tx;
    if (ho < HP) d_w1ctb[ho*ED + eo] = __float2bfloat16(tile[tx][ty]);
}
__global__ void prep_w2t(const float* __restrict__ W2) {
    int o = blockIdx.x, k = threadIdx.x;
    float v = (o < HH && k < HH) ? W2[k*HH + o] : 0.f;
    d_w2t[o*HP + k] = __float2bfloat16(v);
}
__global__ void prep_hihj(const float* __restrict__ g, const float* __restrict__ W1,
                          const float* __restrict__ b1) {
    __shared__ float gs[8][256];
    __shared__ float red[4][8][160];
    const int n0 = blockIdx.x * 8, b = blockIdx.y, z = blockIdx.z;
    const int h = threadIdx.x, s = threadIdx.y;
    const int t = s*160 + h;
    for (int idx = t; idx < 8*256; idx += 640) {
        int row = idx >> 8, e = idx & 255;
        gs[row][e] = g[(size_t)(b*NQ + n0 + row)*ED + z*256 + e];
    }
    __syncthreads();
    float a1[8], a2[8];
    #pragma unroll
    for (int r = 0; r < 8; r++) { a1[r] = 0.f; a2[r] = 0.f; }
    if (h < HH) {
        const int ebase = z*256 + s*64;
        const float* pa = W1 + (size_t)ebase*HH + h;
        const float* pb = W1 + (size_t)(ED + ebase)*HH + h;
        const float* gp = &gs[0][s*64];
        #pragma unroll 4
        for (int el = 0; el < 64; el++) {
            float wa = pa[(size_t)el*HH];
            float wb = pb[(size_t)el*HH];
            #pragma unroll
            for (int r = 0; r < 8; r++) {
                float ge = gp[r*256 + el];
                a1[r] = fmaf(ge, wa, a1[r]);
                a2[r] = fmaf(ge, wb, a2[r]);
            }
        }
    }
    #pragma unroll
    for (int r = 0; r < 8; r++) red[s][r][h] = a1[r];
    __syncthreads();
    if (s == 0 && h < HP) {
        #pragma unroll
        for (int r = 0; r < 8; r++) {
            float v = 0.f;
            if (h < HH) {
                v = red[0][r][h] + red[1][r][h] + red[2][r][h] + red[3][r][h];
                if (z == 0) v += b1[h];
            }
            d_hip[z*(BB*NQ*HP) + (b*NQ + n0 + r)*HP + h] = v;
        }
    }
    __syncthreads();
    #pragma unroll
    for (int r = 0; r < 8; r++) red[s][r][h] = a2[r];
    __syncthreads();
    if (s == 0 && h < HP) {
        #pragma unroll
        for (int r = 0; r < 8; r++) {
            float v = 0.f;
            if (h < HH)
                v = red[0][r][h] + red[1][r][h] + red[2][r][h] + red[3][r][h];
            d_hjp[z*(BB*NQ*HP) + (b*NQ + n0 + r)*HP + h] = v;
        }
    }
}

// ---------------- main kernel: pipelined stage-1 + 8m x 2n warp tiling ----------------
__global__ __launch_bounds__(512, 1)
void pair_pipe2_kernel(const float* __restrict__ g,
                       const float* __restrict__ m,
                       const float* __restrict__ b2,
                       const float* __restrict__ W3,
                       const float* __restrict__ b3,
                       float* __restrict__ out) {
    extern __shared__ char smc[];
    const int t = threadIdx.x, w = t >> 5, lane = t & 31;
    const int mg = w >> 1, ng = w & 1;
    const int b = blockIdx.y;
    int I = 0, rem = blockIdx.x;
    while (rem >= 16 - I) { rem -= 16 - I; I++; }
    const int J = I + rem;
    const int i0 = I << 4, j0 = J << 4;
    const bool diag = (I == J);

    __nv_bfloat16* his = (__nv_bfloat16*)(smc + SM_HIS);
    __nv_bfloat16* hjs = (__nv_bfloat16*)(smc + SM_HJS);
    float* b2s  = (float*)(smc + SM_B2S);
    float* w3s  = (float*)(smc + SM_W3S);
    float* mIs  = (float*)(smc + SM_MIS);
    float* mJs  = (float*)(smc + SM_MJS);
    float* sred = (float*)(smc + SM_SRED);
    char* A1p[2] = { smc + SM_U + OFF_A10, smc + SM_U + OFF_A11 };
    char* B1   = smc + SM_U + OFF_B1;
    char* Gp[2] = { smc + SM_U + OFF_G0, smc + SM_U + OFF_G1 };
    char* W2s  = smc + SM_U + OFF_W2;     // alias A10
    char* HtA  = smc + SM_U + OFF_HA;     // alias (post-stage-1)
    char* HtB  = smc + SM_U + OFF_HB;

    // ---- tables ----
    for (int idx = t; idx < 16*HP; idx += 512) {
        int r = idx / HP, h = idx - r*HP;
        int io = (b*NQ + i0 + r)*HP + h;
        int jo = (b*NQ + j0 + r)*HP + h;
        his[r*HP + h]        = __float2bfloat16(d_hip[io] + d_hip[BB*NQ*HP + io]);
        his[(16 + r)*HP + h] = __float2bfloat16(d_hip[jo] + d_hip[BB*NQ*HP + jo]);
        hjs[r*HP + h]        = __float2bfloat16(d_hjp[io] + d_hjp[BB*NQ*HP + io]);
        hjs[(16 + r)*HP + h] = __float2bfloat16(d_hjp[jo] + d_hjp[BB*NQ*HP + jo]);
    }
    for (int idx = t; idx < HP; idx += 512) {
        b2s[idx] = (idx < HH) ? b2[idx] : 0.f;
        w3s[idx] = (idx < HH) ? W3[idx] : 0.f;
    }
    if (t < 16)       mIs[t]      = m[b*NQ + i0 + t];
    else if (t < 32)  mJs[t - 16] = m[b*NQ + j0 + (t - 16)];

    // ---- helpers ----
    auto gload = [&](int chunk, char* Gd) {
        int r = t >> 4, c8 = (t & 15) * 8;
        int row = (r < 16) ? (i0 + r) : (j0 + r - 16);
        const float* gp = g + (size_t)(b*NQ + row)*ED + chunk*128 + c8;
        float4 va = *(const float4*)gp, vb = *(const float4*)(gp + 4);
        uint4 v = { pack_bf2(va.x, va.y), pack_bf2(va.z, va.w),
                    pack_bf2(vb.x, vb.y), pack_bf2(vb.z, vb.w) };
        *(uint4*)(Gd + r*PG + c8*2) = v;
    };
    auto buildA = [&](const char* Gb, char* Adst) {
        const int pr = (w & 7)*32 + lane;
        const int cg0 = (w >= 8) ? 8 : 0;
        const uint4* gi = (const uint4*)(Gb + (pr >> 4)*PG + cg0*16);
        const uint4* gj = (const uint4*)(Gb + (16 + (pr & 15))*PG + cg0*16);
        char* arow = Adst + pr*P1 + cg0*16;
        #pragma unroll
        for (int u = 0; u < 8; u++) {
            uint4 x = gi[u], y = gj[u], v;
            v.x = mulbf2(x.x, y.x); v.y = mulbf2(x.y, y.y);
            v.z = mulbf2(x.z, y.z); v.w = mulbf2(x.w, y.w);
            *(uint4*)(arow + u*16) = v;
        }
    };

    const uint32_t B1a  = smem_u32(B1);
    const uint32_t W2a  = smem_u32(W2s);
    const uint32_t HtAa = smem_u32(HtA);
    const uint32_t HtBa = smem_u32(HtB);
    const int mrow = mg*32 + (lane & 15);
    const uint32_t akhi  = (lane >> 4) << 4;
    const uint32_t brow  = ng*80 + (lane & 7) + ((lane >> 4) << 3);
    const uint32_t bkoff = ((lane >> 3) & 1) << 4;

    float acc[2][10][4];
    #pragma unroll
    for (int a = 0; a < 2; a++)
        #pragma unroll
        for (int n = 0; n < 10; n++)
            #pragma unroll
            for (int k = 0; k < 4; k++) acc[a][n][k] = 0.f;

    // ---- prologue ----
    gload(0, Gp[0]);
    #pragma unroll
    for (int q = 0; q < 5; q++) {
        int idx = q*512 + t;
        if (idx < 2432) {
            int row = idx >> 4, c16 = idx & 15;
            *(uint4*)(B1 + row*P1 + c16*16) = *(const uint4*)(d_w1ctb + row*ED + c16*8);
        }
    }
    __syncthreads();
    buildA(Gp[0], A1p[0]);
    gload(1, Gp[1]);

    float4 pga = {}, pgb = {};
    uint4 pb0 = {}, pb1 = {}, pb2 = {}, pb3 = {}, pb4 = {};

    // ---- pipelined stage-1 ----
    #pragma unroll
    for (int c = 0; c < 4; c++) {
        __syncthreads();
        if (c < 2) {
            int r = t >> 4, c8 = (t & 15) * 8;
            int row = (r < 16) ? (i0 + r) : (j0 + r - 16);
            const float* gp = g + (size_t)(b*NQ + row)*ED + (c + 2)*128 + c8;
            pga = *(const float4*)gp; pgb = *(const float4*)(gp + 4);
        }
        if (c < 3) {
            const __nv_bfloat16* bsrc = d_w1ctb + (c + 1)*128;
            int iq = t;
            if (iq < 2432) { int r = iq >> 4, c16 = iq & 15; pb0 = *(const uint4*)(bsrc + r*ED + c16*8); }
            iq = 512 + t;  { int r = iq >> 4, c16 = iq & 15; pb1 = *(const uint4*)(bsrc + r*ED + c16*8); }
            iq = 1024 + t; { int r = iq >> 4, c16 = iq & 15; pb2 = *(const uint4*)(bsrc + r*ED + c16*8); }
            iq = 1536 + t; { int r = iq >> 4, c16 = iq & 15; pb3 = *(const uint4*)(bsrc + r*ED + c16*8); }
            iq = 2048 + t;
            if (iq < 2432) { int r = iq >> 4, c16 = iq & 15; pb4 = *(const uint4*)(bsrc + r*ED + c16*8); }
        }
        if (c < 3) {
            buildA(Gp[(c + 1) & 1], A1p[(c + 1) & 1]);
        } else {
            // W2 copy into W2s (aliases dead A10; MMA(3) uses A11+B1)
            #pragma unroll
            for (int q = 0; q < 6; q++) {
                int idx = q*512 + t;
                if (idx < HP*19) {
                    int row = idx / 19, c16 = idx - row*19;
                    *(uint4*)(W2s + row*PH + c16*16) = *(const uint4*)(d_w2t + row*HP + c16*8);
                }
            }
        }
        {   // MMA(c) — 2D tiling
            const uint32_t Aa = smem_u32(A1p[c & 1]);
            #pragma unroll
            for (int ks = 0; ks < 8; ks++) {
                uint32_t a0[4], a1[4];
                uint32_t ab = Aa + mrow*P1 + akhi + ks*32;
                ldsm_x4(a0[0], a0[1], a0[2], a0[3], ab);
                ldsm_x4(a1[0], a1[1], a1[2], a1[3], ab + 16*P1);
                uint32_t bb = B1a + brow*P1 + bkoff + ks*32;
                #pragma unroll
                for (int nt = 0; nt < 4; nt++) {
                    uint32_t b0, b1r, b2r, b3r;
                    ldsm_x4(b0, b1r, b2r, b3r, bb + nt*(16*P1));
                    mma16816(acc[0][2*nt],     a0[0], a0[1], a0[2], a0[3], b0, b1r);
                    mma16816(acc[1][2*nt],     a1[0], a1[1], a1[2], a1[3], b0, b1r);
                    mma16816(acc[0][2*nt + 1], a0[0], a0[1], a0[2], a0[3], b2r, b3r);
                    mma16816(acc[1][2*nt + 1], a1[0], a1[1], a1[2], a1[3], b2r, b3r);
                }
                if (ng == 0) {
                    uint32_t b0, b1r, b2r, b3r;
                    ldsm_x4(b0, b1r, b2r, b3r, bb + 4*(16*P1));
                    mma16816(acc[0][8], a0[0], a0[1], a0[2], a0[3], b0, b1r);
                    mma16816(acc[1][8], a1[0], a1[1], a1[2], a1[3], b0, b1r);
                    mma16816(acc[0][9], a0[0], a0[1], a0[2], a0[3], b2r, b3r);
                    mma16816(acc[1][9], a1[0], a1[1], a1[2], a1[3], b2r, b3r);
                } else {
                    uint32_t b0, b1r;
                    ldsm_x2(b0, b1r, B1a + (144 + (lane & 7))*P1 + bkoff + ks*32);
                    mma16816(acc[0][8], a0[0], a0[1], a0[2], a0[3], b0, b1r);
                    mma16816(acc[1][8], a1[0], a1[1], a1[2], a1[3], b0, b1r);
                }
            }
        }
        __syncthreads();
        if (c < 3) {
            int idx = t;
            if (idx < 2432) { int r = idx >> 4, c16 = idx & 15; *(uint4*)(B1 + r*P1 + c16*16) = pb0; }
            idx = 512 + t;  { int r = idx >> 4, c16 = idx & 15; *(uint4*)(B1 + r*P1 + c16*16) = pb1; }
            idx = 1024 + t; { int r = idx >> 4, c16 = idx & 15; *(uint4*)(B1 + r*P1 + c16*16) = pb2; }
            idx = 1536 + t; { int r = idx >> 4, c16 = idx & 15; *(uint4*)(B1 + r*P1 + c16*16) = pb3; }
            idx = 2048 + t;
            if (idx < 2432) { int r = idx >> 4, c16 = idx & 15; *(uint4*)(B1 + r*P1 + c16*16) = pb4; }
        }
        if (c < 2) {
            int r = t >> 4, c8 = (t & 15) * 8;
            uint4 v = { pack_bf2(pga.x, pga.y), pack_bf2(pga.z, pga.w),
                        pack_bf2(pgb.x, pgb.y), pack_bf2(pgb.z, pgb.w) };
            *(uint4*)(Gp[c & 1] + r*PG + c8*2) = v;
        }
    }

    // ---- epilogue 1: hA -> HtA, hB -> HtB ----
    {
        const int ntl = ng ? 9 : 10;
        #pragma unroll
        for (int mt = 0; mt < 2; mt++) {
            #pragma unroll
            for (int rh = 0; rh < 2; rh++) {
                const int pr = mg*32 + mt*16 + rh*8 + (lane >> 2);
                const int ii = pr >> 4, jj = pr & 15;
                const __nv_bfloat16* hiI = his + ii*HP;
                const __nv_bfloat16* hjJ = hjs + (16 + jj)*HP;
                const __nv_bfloat16* hiJ = his + (16 + jj)*HP;
                const __nv_bfloat16* hjI = hjs + ii*HP;
                char* rowA = HtA + pr*PH;
                char* rowB = HtB + pr*PH;
                #pragma unroll
                for (int nt = 0; nt < 10; nt++) {
                    if (nt >= ntl) break;
                    int col = ng*80 + nt*8 + (lane & 3)*2;
                    float d0 = acc[mt][nt][rh*2 + 0];
                    float d1 = acc[mt][nt][rh*2 + 1];
                    float2 u = bf2_to_f2(*(const uint32_t*)(hiI + col));
                    float2 v = bf2_to_f2(*(const uint32_t*)(hjJ + col));
                    *(uint32_t*)(rowA + col*2) = pack_bf2(
                        fmaxf(d0 + u.x + v.x, 0.f), fmaxf(d1 + u.y + v.y, 0.f));
                    if (!diag) {
                        float2 p = bf2_to_f2(*(const uint32_t*)(hiJ + col));
                        float2 q = bf2_to_f2(*(const uint32_t*)(hjI + col));
                        *(uint32_t*)(rowB + col*2) = pack_bf2(
                            fmaxf(d0 + p.x + q.x, 0.f), fmaxf(d1 + p.y + q.y, 0.f));
                    }
                }
            }
        }
    }
    __syncthreads();

    // ---- stage 2 (1-2 passes) ----
    const float b3v = b3[0];
    const int npass = diag ? 1 : 2;
    for (int pass = 0; pass < npass; pass++) {
        const uint32_t Ha = pass ? HtBa : HtAa;
        #pragma unroll
        for (int n = 0; n < 10; n++)
            #pragma unroll
            for (int k = 0; k < 4; k++) { acc[0][n][k] = 0.f; acc[1][n][k] = 0.f; }

        for (int ks = 0; ks < 9; ks++) {
            uint32_t a0[4], a1[4];
            uint32_t ab = Ha + mrow*PH + akhi + ks*32;
            ldsm_x4(a0[0], a0[1], a0[2], a0[3], ab);
            ldsm_x4(a1[0], a1[1], a1[2], a1[3], ab + 16*PH);
            uint32_t bb = W2a + brow*PH + bkoff + ks*32;
            #pragma unroll
            for (int nt = 0; nt < 4; nt++) {
                uint32_t b0, b1r, b2r, b3r;
                ldsm_x4(b0, b1r, b2r, b3r, bb + nt*(16*PH));
                mma16816(acc[0][2*nt],     a0[0], a0[1], a0[2], a0[3], b0, b1r);
                mma16816(acc[1][2*nt],     a1[0], a1[1], a1[2], a1[3], b0, b1r);
                mma16816(acc[0][2*nt + 1], a0[0], a0[1], a0[2], a0[3], b2r, b3r);
                mma16816(acc[1][2*nt + 1], a1[0], a1[1], a1[2], a1[3], b2r, b3r);
            }
            if (ng == 0) {
                uint32_t b0, b1r, b2r, b3r;
                ldsm_x4(b0, b1r, b2r, b3r, bb + 4*(16*PH));
                mma16816(acc[0][8], a0[0], a0[1], a0[2], a0[3], b0, b1r);
                mma16816(acc[1][8], a1[0], a1[1], a1[2], a1[3], b0, b1r);
                mma16816(acc[0][9], a0[0], a0[1], a0[2], a0[3], b2r, b3r);
                mma16816(acc[1][9], a1[0], a1[1], a1[2], a1[3], b2r, b3r);
            } else {
                uint32_t b0, b1r;
                ldsm_x2(b0, b1r, W2a + (144 + (lane & 7))*PH + bkoff + ks*32);
                mma16816(acc[0][8], a0[0], a0[1], a0[2], a0[3], b0, b1r);
                mma16816(acc[1][8], a1[0], a1[1], a1[2], a1[3], b0, b1r);
            }
        }
        {   // k8 tail (cols 144-151, byte 288)
            uint32_t ta0, ta1, tb0, tb1;
            uint32_t ab = Ha + mrow*PH + 288;
            ldsm_x2(ta0, ta1, ab);
            ldsm_x2(tb0, tb1, ab + 16*PH);
            if (ng == 0) {
                #pragma unroll
                for (int q = 0; q < 2; q++) {
                    uint32_t b0, b1r, b2r, b3r;
                    ldsm_x4(b0, b1r, b2r, b3r,
                            W2a + (uint32_t)((q*32 + (lane >> 3)*8 + (lane & 7))*PH + 288));
                    mma16808(acc[0][4*q + 0], ta0, ta1, b0);
                    mma16808(acc[1][4*q + 0], tb0, tb1, b0);
                    mma16808(acc[0][4*q + 1], ta0, ta1, b1r);
                    mma16808(acc[1][4*q + 1], tb0, tb1, b1r);
                    mma16808(acc[0][4*q + 2], ta0, ta1, b2r);
                    mma16808(acc[1][4*q + 2], tb0, tb1, b2r);
                    mma16808(acc[0][4*q + 3], ta0, ta1, b3r);
                    mma16808(acc[1][4*q + 3], tb0, tb1, b3r);
                }
                uint32_t b0, b1r;
                ldsm_x2(b0, b1r,
                        W2a + (uint32_t)((64 + ((lane >> 3) & 1)*8 + (lane & 7))*PH + 288));
                mma16808(acc[0][8], ta0, ta1, b0);
                mma16808(acc[1][8], tb0, tb1, b0);
                mma16808(acc[0][9], ta0, ta1, b1r);
                mma16808(acc[1][9], tb0, tb1, b1r);
            } else {
                #pragma unroll
                for (int q = 0; q < 2; q++) {
                    uint32_t b0, b1r, b2r, b3r;
                    ldsm_x4(b0, b1r, b2r, b3r,
                            W2a + (uint32_t)((80 + q*32 + (lane >> 3)*8 + (lane & 7))*PH + 288));
                    mma16808(acc[0][4*q + 0], ta0, ta1, b0);
                    mma16808(acc[1][4*q + 0], tb0, tb1, b0);
                    mma16808(acc[0][4*q + 1], ta0, ta1, b1r);
                    mma16808(acc[1][4*q + 1], tb0, tb1, b1r);
                    mma16808(acc[0][4*q + 2], ta0, ta1, b2r);
                    mma16808(acc[1][4*q + 2], tb0, tb1, b2r);
                    mma16808(acc[0][4*q + 3], ta0, ta1, b3r);
                    mma16808(acc[1][4*q + 3], tb0, tb1, b3r);
                }
                uint32_t bx;
                ldsm_x1(bx, W2a + (uint32_t)((144 + (lane & 7))*PH + 288));
                mma16808(acc[0][8], ta0, ta1, bx);
                mma16808(acc[1][8], tb0, tb1, bx);
            }
        }

        // epilogue 2: partial W3 dot -> sred reduce across ng
        const int ntl = ng ? 9 : 10;
        #pragma unroll
        for (int mt = 0; mt < 2; mt++) {
            #pragma unroll
            for (int rh = 0; rh < 2; rh++) {
                float s = 0.f;
                #pragma unroll
                for (int nt = 0; nt < 10; nt++) {
                    if (nt >= ntl) break;
                    int col = ng*80 + nt*8 + (lane & 3)*2;
                    float v0 = fmaxf(acc[mt][nt][rh*2 + 0] + b2s[col],     0.f);
                    float v1 = fmaxf(acc[mt][nt][rh*2 + 1] + b2s[col + 1], 0.f);
                    s = fmaf(v0, w3s[col], s);
                    s = fmaf(v1, w3s[col + 1], s);
                }
                s += __shfl_xor_sync(0xFFFFFFFF, s, 1);
                s += __shfl_xor_sync(0xFFFFFFFF, s, 2);
                if ((lane & 3) == 0) {
                    int pr = mg*32 + mt*16 + rh*8 + (lane >> 2);
                    sred[pr*2 + ng] = s;
                }
            }
        }
        __syncthreads();
        if (t < 256) {
            int pr = t, ii = pr >> 4, jj = pr & 15;
            float pair = sred[pr*2] + sred[pr*2 + 1] + b3v;
            float res = (mIs[ii] + mJs[jj] + pair) * (1.0f/3.0f);
            if (pass == 0)
                out[(size_t)(b*NQ + i0 + ii)*NQ + j0 + jj] = res;
            else
                out[(size_t)(b*NQ + j0 + jj)*NQ + i0 + ii] = res;
        }
        __syncthreads();
    }
}

// ---------------------------------------------------------------------------
extern "C" void kernel_launch(void* const* d_in, const int* in_sizes, int n_in,
                              void* d_out, int out_size) {
    const float* g  = (const float*)d_in[0];
    const float* m  = (const float*)d_in[1];
    const float* W1 = (const float*)d_in[2];
    const float* b1 = (const float*)d_in[3];
    const float* W2 = (const float*)d_in[4];
    const float* b2 = (const float*)d_in[5];
    const float* W3 = (const float*)d_in[6];
    const float* b3 = (const float*)d_in[7];
    float* out = (float*)d_out;

    cudaFuncSetAttribute(pair_pipe2_kernel,
                         cudaFuncAttributeMaxDynamicSharedMemorySize, SMEM_BYTES);

    prep_w1ct<<<dim3(ED/32, 5), dim3(32, 32)>>>(W1);
    prep_w2t<<<HP, HP>>>(W2);
    prep_hihj<<<dim3(NQ/8, BB, 2), dim3(160, 4)>>>(g, W1, b1);
    pair_pipe2_kernel<<<dim3(136, BB), 512, SMEM_BYTES>>>(g, m, b2, W3, b3, out);
}

// round 12
// speedup vs baseline: 1.0786x; 1.0786x over previous
#include <cuda_runtime.h>
#include <cuda_bf16.h>
#include <cstdint>

#define BB 2
#define NQ 256
#define ED 512
#define HH 150
#define HP 152

#define P1 272            // B1 pitch (bytes)
#define PH 304            // HtB/W2s pitch (bytes)
#define PG2 1040          // g staging pitch (bytes): 260 words, %32==4 -> frag-read conflict-free

// ---------------- device scratch ----------------
__device__ __nv_bfloat16 d_w1ctb[HP*ED];      // W1c^T bf16 [h][e]
__device__ __nv_bfloat16 d_w2t[HP*HP];        // W2^T bf16 [o][k]
__device__ float         d_hip[2*BB*NQ*HP];   // hi+b1 partials
__device__ float         d_hjp[2*BB*NQ*HP];   // hj partials

// ---------------- smem layout (bytes) ----------------
#define SM_HIS  0                       // 9728
#define SM_HJS  9728                    // -> 19456
#define SM_B2S  19456                   // 608
#define SM_W3S  20064                   // 608
#define SM_MIS  20672                   // 64
#define SM_MJS  20736                   // 64
#define SM_U    20800
// stage-1: [G 33280][B0 41344][B1 41344] = 115968
#define OFF_G   0
#define OFF_B0  33280
#define OFF_B1b 74624
// stage-2 aliases: W2s over G+B0-head; HtB over B0-tail+B1b
#define OFF_W2  0                       // 46208
#define OFF_HB  46208                   // 77824 -> 124032
#define SMEM_BYTES (SM_U + 124032)      // 144832

__device__ __forceinline__ uint32_t smem_u32(const void* p) {
    uint32_t a;
    asm("{ .reg .u64 t; cvta.to.shared.u64 t, %1; cvt.u32.u64 %0, t; }" : "=r"(a) : "l"(p));
    return a;
}
__device__ __forceinline__ void ldsm_x4(uint32_t& r0, uint32_t& r1, uint32_t& r2, uint32_t& r3,
                                        uint32_t addr) {
    asm volatile("ldmatrix.sync.aligned.m8n8.x4.shared.b16 {%0,%1,%2,%3}, [%4];"
                 : "=r"(r0), "=r"(r1), "=r"(r2), "=r"(r3) : "r"(addr));
}
__device__ __forceinline__ void ldsm_x2(uint32_t& r0, uint32_t& r1, uint32_t addr) {
    asm volatile("ldmatrix.sync.aligned.m8n8.x2.shared.b16 {%0,%1}, [%2];"
                 : "=r"(r0), "=r"(r1) : "r"(addr));
}
__device__ __forceinline__ void ldsm_x1(uint32_t& r0, uint32_t addr) {
    asm volatile("ldmatrix.sync.aligned.m8n8.x1.shared.b16 {%0}, [%1];"
                 : "=r"(r0) : "r"(addr));
}
__device__ __forceinline__ void mma16816(float* d, uint32_t a0, uint32_t a1, uint32_t a2,
                                         uint32_t a3, uint32_t b0, uint32_t b1) {
    asm volatile("mma.sync.aligned.m16n8k16.row.col.f32.bf16.bf16.f32 "
                 "{%0,%1,%2,%3}, {%4,%5,%6,%7}, {%8,%9}, {%0,%1,%2,%3};"
                 : "+f"(d[0]), "+f"(d[1]), "+f"(d[2]), "+f"(d[3])
                 : "r"(a0), "r"(a1), "r"(a2), "r"(a3), "r"(b0), "r"(b1));
}
__device__ __forceinline__ void mma16808(float* d, uint32_t a0, uint32_t a1, uint32_t b0) {
    asm volatile("mma.sync.aligned.m16n8k8.row.col.f32.bf16.bf16.f32 "
                 "{%0,%1,%2,%3}, {%4,%5}, {%6}, {%0,%1,%2,%3};"
                 : "+f"(d[0]), "+f"(d[1]), "+f"(d[2]), "+f"(d[3])
                 : "r"(a0), "r"(a1), "r"(b0));
}
__device__ __forceinline__ uint32_t mulbf2(uint32_t a, uint32_t b) {
    uint32_t r;
    asm("mul.bf16x2 %0, %1, %2;" : "=r"(r) : "r"(a), "r"(b));
    return r;
}
__device__ __forceinline__ float2 bf2_to_f2(uint32_t u) {
    __nv_bfloat162 h = *(__nv_bfloat162*)&u;
    return __bfloat1622float2(h);
}
__device__ __forceinline__ uint32_t pack_bf2(float x, float y) {
    __nv_bfloat162 p = __floats2bfloat162_rn(x, y);
    return *(uint32_t*)&p;
}

// ---------------- prekernels ----------------
__global__ void prep_w1ct(const float* __restrict__ W1) {
    __shared__ float tile[32][33];
    int e0 = blockIdx.x * 32, h0 = blockIdx.y * 32;
    int tx = threadIdx.x, ty = threadIdx.y;
    int h = h0 + tx, e = e0 + ty;
    tile[ty][tx] = (h < HH) ? W1[(size_t)(2*ED + e)*HH + h] : 0.f;
    __syncthreads();
    int ho = h0 + ty, eo = e0 + tx;
    if (ho < HP) d_w1ctb[ho*ED + eo] = __float2bfloat16(tile[tx][ty]);
}
__global__ void prep_w2t(const float* __restrict__ W2) {
    int o = blockIdx.x, k = threadIdx.x;
    float v = (o < HH && k < HH) ? W2[k*HH + o] : 0.f;
    d_w2t[o*HP + k] = __float2bfloat16(v);
}
__global__ void prep_hihj(const float* __restrict__ g, const float* __restrict__ W1,
                          const float* __restrict__ b1) {
    __shared__ float gs[8][256];
    __shared__ float red[4][8][160];
    const int n0 = blockIdx.x * 8, b = blockIdx.y, z = blockIdx.z;
    const int h = threadIdx.x, s = threadIdx.y;
    const int t = s*160 + h;
    for (int idx = t; idx < 8*256; idx += 640) {
        int row = idx >> 8, e = idx & 255;
        gs[row][e] = g[(size_t)(b*NQ + n0 + row)*ED + z*256 + e];
    }
    __syncthreads();
    float a1[8], a2[8];
    #pragma unroll
    for (int r = 0; r < 8; r++) { a1[r] = 0.f; a2[r] = 0.f; }
    if (h < HH) {
        const int ebase = z*256 + s*64;
        const float* pa = W1 + (size_t)ebase*HH + h;
        const float* pb = W1 + (size_t)(ED + ebase)*HH + h;
        const float* gp = &gs[0][s*64];
        #pragma unroll 4
        for (int el = 0; el < 64; el++) {
            float wa = pa[(size_t)el*HH];
            float wb = pb[(size_t)el*HH];
            #pragma unroll
            for (int r = 0; r < 8; r++) {
                float ge = gp[r*256 + el];
                a1[r] = fmaf(ge, wa, a1[r]);
                a2[r] = fmaf(ge, wb, a2[r]);
            }
        }
    }
    #pragma unroll
    for (int r = 0; r < 8; r++) red[s][r][h] = a1[r];
    __syncthreads();
    if (s == 0 && h < HP) {
        #pragma unroll
        for (int r = 0; r < 8; r++) {
            float v = 0.f;
            if (h < HH) {
                v = red[0][r][h] + red[1][r][h] + red[2][r][h] + red[3][r][h];
                if (z == 0) v += b1[h];
            }
            d_hip[z*(BB*NQ*HP) + (b*NQ + n0 + r)*HP + h] = v;
        }
    }
    __syncthreads();
    #pragma unroll
    for (int r = 0; r < 8; r++) red[s][r][h] = a2[r];
    __syncthreads();
    if (s == 0 && h < HP) {
        #pragma unroll
        for (int r = 0; r < 8; r++) {
            float v = 0.f;
            if (h < HH)
                v = red[0][r][h] + red[1][r][h] + red[2][r][h] + red[3][r][h];
            d_hjp[z*(BB*NQ*HP) + (b*NQ + n0 + r)*HP + h] = v;
        }
    }
}

// ---------------- main kernel: register A-fragments, double-buffered B ----------------
__global__ __launch_bounds__(512, 1)
void pair_frag_kernel(const float* __restrict__ g,
                      const float* __restrict__ m,
                      const float* __restrict__ b2,
                      const float* __restrict__ W3,
                      const float* __restrict__ b3,
                      float* __restrict__ out) {
    extern __shared__ char smc[];
    const int t = threadIdx.x, w = t >> 5, lane = t & 31;
    const int b = blockIdx.y;
    int I = 0, rem = blockIdx.x;
    while (rem >= 16 - I) { rem -= 16 - I; I++; }
    const int J = I + rem;
    const int i0 = I << 4, j0 = J << 4;
    const bool diag = (I == J);

    __nv_bfloat16* his = (__nv_bfloat16*)(smc + SM_HIS);
    __nv_bfloat16* hjs = (__nv_bfloat16*)(smc + SM_HJS);
    float* b2s = (float*)(smc + SM_B2S);
    float* w3s = (float*)(smc + SM_W3S);
    float* mIs = (float*)(smc + SM_MIS);
    float* mJs = (float*)(smc + SM_MJS);
    char* Gc  = smc + SM_U + OFF_G;
    char* Bp[2] = { smc + SM_U + OFF_B0, smc + SM_U + OFF_B1b };
    char* W2s = smc + SM_U + OFF_W2;     // alias G + B0 head (dead post stage-1)
    char* HtB = smc + SM_U + OFF_HB;     // alias B0 tail + B1b (dead post stage-1)

    // ---- tables ----
    for (int idx = t; idx < 16*HP; idx += 512) {
        int r = idx / HP, h = idx - r*HP;
        int io = (b*NQ + i0 + r)*HP + h;
        int jo = (b*NQ + j0 + r)*HP + h;
        his[r*HP + h]        = __float2bfloat16(d_hip[io] + d_hip[BB*NQ*HP + io]);
        his[(16 + r)*HP + h] = __float2bfloat16(d_hip[jo] + d_hip[BB*NQ*HP + jo]);
        hjs[r*HP + h]        = __float2bfloat16(d_hjp[io] + d_hjp[BB*NQ*HP + io]);
        hjs[(16 + r)*HP + h] = __float2bfloat16(d_hjp[jo] + d_hjp[BB*NQ*HP + jo]);
    }
    for (int idx = t; idx < HP; idx += 512) {
        b2s[idx] = (idx < HH) ? b2[idx] : 0.f;
        w3s[idx] = (idx < HH) ? W3[idx] : 0.f;
    }
    if (t < 16)       mIs[t]      = m[b*NQ + i0 + t];
    else if (t < 32)  mJs[t - 16] = m[b*NQ + j0 + (t - 16)];

    // ---- stage g (all 512 cols) into G: rows 0-15 = I-rows, 16-31 = J-rows ----
    {
        int r = t >> 4;
        int grow = (r < 16) ? (i0 + r) : (j0 + (r - 16));
        int c0 = (t & 15) * 32;
        const float* gp = g + (size_t)(b*NQ + grow)*ED + c0;
        char* dst = Gc + r*PG2 + c0*2;
        #pragma unroll
        for (int q = 0; q < 4; q++) {
            float4 va = *(const float4*)(gp + q*8);
            float4 vb = *(const float4*)(gp + q*8 + 4);
            uint4 v = { pack_bf2(va.x, va.y), pack_bf2(va.z, va.w),
                        pack_bf2(vb.x, vb.y), pack_bf2(vb.z, vb.w) };
            *(uint4*)(dst + q*16) = v;
        }
    }
    // ---- B(0) ----
    #pragma unroll
    for (int q = 0; q < 5; q++) {
        int idx = q*512 + t;
        if (idx < 2432) {
            int row = idx >> 4, c16 = idx & 15;
            *(uint4*)(Bp[0] + row*P1 + c16*16) = *(const uint4*)(d_w1ctb + row*ED + c16*8);
        }
    }
    __syncthreads();

    float acc[19][4];
    #pragma unroll
    for (int n = 0; n < 19; n++)
        #pragma unroll
        for (int k = 0; k < 4; k++) acc[n][k] = 0.f;

    // per-lane A-fragment source pointers (gi row fixed = warp's I-row)
    const char* gip  = Gc + w*PG2 + (lane & 3)*4;
    const char* gjAp = Gc + (16 + (lane >> 2))*PG2 + (lane & 3)*4;
    const char* gjBp = gjAp + 8*PG2;
    const uint32_t brow  = (lane & 7) + ((lane >> 4) << 3);
    const uint32_t bkoff = ((lane >> 3) & 1) << 4;
    const int mw = w << 4;

    // ---- stage 1: 4 K-chunks, double-buffered B, zero A staging ----
    #pragma unroll
    for (int c = 0; c < 4; c++) {
        if (c < 3) {   // fill idle B buffer while MMA(c) runs
            char* Bd = Bp[(c + 1) & 1];
            const __nv_bfloat16* bsrc = d_w1ctb + (c + 1)*128;
            #pragma unroll
            for (int q = 0; q < 5; q++) {
                int idx = q*512 + t;
                if (idx < 2432) {
                    int row = idx >> 4, c16 = idx & 15;
                    *(uint4*)(Bd + row*P1 + c16*16) = *(const uint4*)(bsrc + row*ED + c16*8);
                }
            }
        }
        const uint32_t Ba = smem_u32(Bp[c & 1]);
        #pragma unroll
        for (int ks = 0; ks < 8; ks++) {
            const int eb = c*256 + ks*32;     // byte offset into g row
            uint32_t gi0 = *(const uint32_t*)(gip + eb);
            uint32_t gi1 = *(const uint32_t*)(gip + eb + 16);
            uint32_t ga0 = *(const uint32_t*)(gjAp + eb);
            uint32_t ga1 = *(const uint32_t*)(gjAp + eb + 16);
            uint32_t gb0 = *(const uint32_t*)(gjBp + eb);
            uint32_t gb1 = *(const uint32_t*)(gjBp + eb + 16);
            uint32_t a0 = mulbf2(gi0, ga0);
            uint32_t a1 = mulbf2(gi0, gb0);
            uint32_t a2 = mulbf2(gi1, ga1);
            uint32_t a3 = mulbf2(gi1, gb1);
            uint32_t bb = Ba + brow*P1 + bkoff + ks*32;
            #pragma unroll
            for (int np = 0; np < 9; np++) {
                uint32_t b0, b1r, b2r, b3r;
                ldsm_x4(b0, b1r, b2r, b3r, bb + np*(16*P1));
                mma16816(acc[2*np],     a0, a1, a2, a3, b0, b1r);
                mma16816(acc[2*np + 1], a0, a1, a2, a3, b2r, b3r);
            }
            uint32_t b0, b1r;
            ldsm_x2(b0, b1r, Ba + (144 + (lane & 7))*P1 + bkoff + ks*32);
            mma16816(acc[18], a0, a1, a2, a3, b0, b1r);
        }
        __syncthreads();
    }

    // ---- epilogue 1: hA frags in regs; hB -> HtB; W2 -> W2s (aliases dead G/B) ----
    uint32_t hA[19][2];
    {
        #pragma unroll
        for (int q = 0; q < 6; q++) {
            int idx = q*512 + t;
            if (idx < HP*19) {
                int row = idx / 19, c16 = idx - row*19;
                *(uint4*)(W2s + row*PH + c16*16) = *(const uint4*)(d_w2t + row*HP + c16*8);
            }
        }
        const __nv_bfloat16* hiIr = his + w*HP;
        const __nv_bfloat16* hjIr = hjs + w*HP;
        const int jlo = lane >> 2, jhi = jlo + 8;
        const __nv_bfloat16* hjJl = hjs + (16 + jlo)*HP;
        const __nv_bfloat16* hjJh = hjs + (16 + jhi)*HP;
        const __nv_bfloat16* hiJl = his + (16 + jlo)*HP;
        const __nv_bfloat16* hiJh = his + (16 + jhi)*HP;
        char* rowBlo = HtB + (mw + jlo)*PH;
        char* rowBhi = HtB + (mw + jhi)*PH;
        #pragma unroll
        for (int nt = 0; nt < 19; nt++) {
            int col = nt*8 + (lane & 3)*2;
            float2 hiI = bf2_to_f2(*(const uint32_t*)(hiIr + col));
            float2 hjl = bf2_to_f2(*(const uint32_t*)(hjJl + col));
            float2 hjh = bf2_to_f2(*(const uint32_t*)(hjJh + col));
            hA[nt][0] = pack_bf2(fmaxf(acc[nt][0] + hiI.x + hjl.x, 0.f),
                                 fmaxf(acc[nt][1] + hiI.y + hjl.y, 0.f));
            hA[nt][1] = pack_bf2(fmaxf(acc[nt][2] + hiI.x + hjh.x, 0.f),
                                 fmaxf(acc[nt][3] + hiI.y + hjh.y, 0.f));
            if (!diag) {
                float2 hjI = bf2_to_f2(*(const uint32_t*)(hjIr + col));
                float2 hil = bf2_to_f2(*(const uint32_t*)(hiJl + col));
                float2 hih = bf2_to_f2(*(const uint32_t*)(hiJh + col));
                *(uint32_t*)(rowBlo + col*2) =
                    pack_bf2(fmaxf(acc[nt][0] + hil.x + hjI.x, 0.f),
                             fmaxf(acc[nt][1] + hil.y + hjI.y, 0.f));
                *(uint32_t*)(rowBhi + col*2) =
                    pack_bf2(fmaxf(acc[nt][2] + hih.x + hjI.x, 0.f),
                             fmaxf(acc[nt][3] + hih.y + hjI.y, 0.f));
            }
        }
    }
    __syncthreads();   // W2s ready

    // ---- stage 2 ----
    const uint32_t W2a  = smem_u32(W2s);
    const uint32_t HtBa = smem_u32(HtB);
    const uint32_t aoffH = (mw + (lane & 15))*PH + ((lane >> 4) << 4);
    const float b3v = b3[0];

    auto stage2 = [&](bool useHtB, int pass) {
        float sl = 0.f, sh = 0.f;
        #pragma unroll
        for (int hf = 0; hf < 2; hf++) {
            float a2c[10][4];
            #pragma unroll
            for (int n = 0; n < 10; n++)
                #pragma unroll
                for (int k = 0; k < 4; k++) a2c[n][k] = 0.f;

            #pragma unroll
            for (int ks = 0; ks < 9; ks++) {
                uint32_t a0, a1, a2, a3;
                if (useHtB) {
                    ldsm_x4(a0, a1, a2, a3, HtBa + aoffH + ks*32);
                } else {
                    a0 = hA[2*ks][0]; a1 = hA[2*ks][1];
                    a2 = hA[2*ks + 1][0]; a3 = hA[2*ks + 1][1];
                }
                if (hf == 0) {
                    uint32_t bb = W2a + brow*PH + bkoff + ks*32;
                    #pragma unroll
                    for (int np = 0; np < 5; np++) {
                        uint32_t b0, b1r, b2r, b3r;
                        ldsm_x4(b0, b1r, b2r, b3r, bb + np*(16*PH));
                        mma16816(a2c[2*np],     a0, a1, a2, a3, b0, b1r);
                        mma16816(a2c[2*np + 1], a0, a1, a2, a3, b2r, b3r);
                    }
                } else {
                    uint32_t bb = W2a + (80 + brow)*PH + bkoff + ks*32;
                    #pragma unroll
                    for (int np = 0; np < 4; np++) {
                        uint32_t b0, b1r, b2r, b3r;
                        ldsm_x4(b0, b1r, b2r, b3r, bb + np*(16*PH));
                        mma16816(a2c[2*np],     a0, a1, a2, a3, b0, b1r);
                        mma16816(a2c[2*np + 1], a0, a1, a2, a3, b2r, b3r);
                    }
                    uint32_t b0, b1r;
                    ldsm_x2(b0, b1r, W2a + (144 + (lane & 7))*PH + bkoff + ks*32);
                    mma16816(a2c[8], a0, a1, a2, a3, b0, b1r);
                }
            }
            {   // k8 tail (cols 144-151, byte 288)
                uint32_t ta0, ta1;
                if (useHtB) ldsm_x2(ta0, ta1, HtBa + (mw + (lane & 15))*PH + 288);
                else { ta0 = hA[18][0]; ta1 = hA[18][1]; }
                if (hf == 0) {
                    #pragma unroll
                    for (int q = 0; q < 2; q++) {
                        uint32_t b0, b1r, b2r, b3r;
                        ldsm_x4(b0, b1r, b2r, b3r,
                                W2a + (uint32_t)((q*32 + (lane >> 3)*8 + (lane & 7))*PH + 288));
                        mma16808(a2c[4*q + 0], ta0, ta1, b0);
                        mma16808(a2c[4*q + 1], ta0, ta1, b1r);
                        mma16808(a2c[4*q + 2], ta0, ta1, b2r);
                        mma16808(a2c[4*q + 3], ta0, ta1, b3r);
                    }
                    uint32_t b0, b1r;
                    ldsm_x2(b0, b1r,
                            W2a + (uint32_t)((64 + ((lane >> 3) & 1)*8 + (lane & 7))*PH + 288));
                    mma16808(a2c[8], ta0, ta1, b0);
                    mma16808(a2c[9], ta0, ta1, b1r);
                } else {
                    #pragma unroll
                    for (int q = 0; q < 2; q++) {
                        uint32_t b0, b1r, b2r, b3r;
                        ldsm_x4(b0, b1r, b2r, b3r,
                                W2a + (uint32_t)((80 + q*32 + (lane >> 3)*8 + (lane & 7))*PH + 288));
                        mma16808(a2c[4*q + 0], ta0, ta1, b0);
                        mma16808(a2c[4*q + 1], ta0, ta1, b1r);
                        mma16808(a2c[4*q + 2], ta0, ta1, b2r);
                        mma16808(a2c[4*q + 3], ta0, ta1, b3r);
                    }
                    uint32_t bx;
                    ldsm_x1(bx, W2a + (uint32_t)((144 + (lane & 7))*PH + 288));
                    mma16808(a2c[8], ta0, ta1, bx);
                }
            }
            const int ntl = hf ? 9 : 10;
            #pragma unroll
            for (int nt = 0; nt < 10; nt++) {
                if (nt >= ntl) break;
                int col = hf*80 + nt*8 + (lane & 3)*2;
                sl = fmaf(fmaxf(a2c[nt][0] + b2s[col],     0.f), w3s[col],     sl);
                sl = fmaf(fmaxf(a2c[nt][1] + b2s[col + 1], 0.f), w3s[col + 1], sl);
                sh = fmaf(fmaxf(a2c[nt][2] + b2s[col],     0.f), w3s[col],     sh);
                sh = fmaf(fmaxf(a2c[nt][3] + b2s[col + 1], 0.f), w3s[col + 1], sh);
            }
        }
        sl += __shfl_xor_sync(0xFFFFFFFF, sl, 1);
        sl += __shfl_xor_sync(0xFFFFFFFF, sl, 2);
        sh += __shfl_xor_sync(0xFFFFFFFF, sh, 1);
        sh += __shfl_xor_sync(0xFFFFFFFF, sh, 2);
        if ((lane & 3) == 0) {
            int jlo = lane >> 2, jhi = jlo + 8;
            float rl = (mIs[w] + mJs[jlo] + sl + b3v) * (1.0f/3.0f);
            float rh = (mIs[w] + mJs[jhi] + sh + b3v) * (1.0f/3.0f);
            if (pass == 0) {
                out[(size_t)(b*NQ + i0 + w)*NQ + j0 + jlo] = rl;
                out[(size_t)(b*NQ + i0 + w)*NQ + j0 + jhi] = rh;
            } else {
                out[(size_t)(b*NQ + j0 + jlo)*NQ + i0 + w] = rl;
                out[(size_t)(b*NQ + j0 + jhi)*NQ + i0 + w] = rh;
            }
        }
    };

    stage2(false, 0);
    if (!diag) {
        __syncwarp();
        stage2(true, 1);
    }
}

// ---------------------------------------------------------------------------
extern "C" void kernel_launch(void* const* d_in, const int* in_sizes, int n_in,
                              void* d_out, int out_size) {
    const float* g  = (const float*)d_in[0];
    const float* m  = (const float*)d_in[1];
    const float* W1 = (const float*)d_in[2];
    const float* b1 = (const float*)d_in[3];
    const float* W2 = (const float*)d_in[4];
    const float* b2 = (const float*)d_in[5];
    const float* W3 = (const float*)d_in[6];
    const float* b3 = (const float*)d_in[7];
    float* out = (float*)d_out;

    cudaFuncSetAttribute(pair_frag_kernel,
                         cudaFuncAttributeMaxDynamicSharedMemorySize, SMEM_BYTES);

    prep_w1ct<<<dim3(ED/32, 5), dim3(32, 32)>>>(W1);
    prep_w2t<<<HP, HP>>>(W2);
    prep_hihj<<<dim3(NQ/8, BB, 2), dim3(160, 4)>>>(g, W1, b1);
    pair_frag_kernel<<<dim3(136, BB), 512, SMEM_BYTES>>>(g, m, b2, W3, b3, out);
}